// round 1
// baseline (speedup 1.0000x reference)
#include <cuda_runtime.h>
#include <cuda_bf16.h>
#include <math.h>

// Problem constants
#define BATCH 4
#define SEQ   4096
#define DIN   2048
#define PAIRS 256          // DD_PAIRS
#define MROWS (BATCH*SEQ)  // 16384
#define NCHUNK 64
#define TCHUNK (SEQ/NCHUNK) // 64

// Scratch (device globals: no allocation allowed)
__device__ float g_delta[MROWS * PAIRS];          // 16.8 MB  [m][p]
__device__ float g_csum [BATCH * NCHUNK * PAIRS]; // chunk sums
__device__ float g_coff [BATCH * NCHUNK * PAIRS]; // exclusive chunk offsets

// ---------------------------------------------------------------------------
// GEMM: delta[m][p] = sum_k x[m][k] * W[p][k] + bias[p]
// BM=128, BP=64, BK=32, 256 threads, 8x4 micro-tile per thread.
// ---------------------------------------------------------------------------
#define BM 128
#define BP 64
#define BK 32
#define PADA 132  // 128+4 (float4-aligned pad)
#define PADB 68   // 64+4

__global__ __launch_bounds__(256, 3)
void gemm_kernel(const float* __restrict__ X, const float* __restrict__ W,
                 const float* __restrict__ bias) {
    __shared__ float As[BK][PADA];
    __shared__ float Bs[BK][PADB];

    const int bm = blockIdx.y * BM;
    const int bp = blockIdx.x * BP;
    const int tid = threadIdx.x;
    const int tx = tid & 15;       // p direction, 16 threads * 4 = 64
    const int ty = tid >> 4;       // m direction, 16 threads * 8 = 128
    const int tm = ty * 8;
    const int tp = tx * 4;

    float acc[8][4];
#pragma unroll
    for (int i = 0; i < 8; i++)
#pragma unroll
        for (int j = 0; j < 4; j++) acc[i][j] = 0.f;

    for (int k0 = 0; k0 < DIN; k0 += BK) {
        // Load A tile: 128x32 floats = 1024 float4, 4 per thread
#pragma unroll
        for (int i = 0; i < 4; i++) {
            int f4 = tid + i * 256;
            int row = f4 >> 3;        // 0..127
            int kq  = f4 & 7;         // 0..7 (k = kq*4)
            float4 v = *(const float4*)&X[(bm + row) * DIN + k0 + kq * 4];
            As[kq*4+0][row] = v.x; As[kq*4+1][row] = v.y;
            As[kq*4+2][row] = v.z; As[kq*4+3][row] = v.w;
        }
        // Load B tile: 64x32 floats = 512 float4, 2 per thread
#pragma unroll
        for (int i = 0; i < 2; i++) {
            int f4 = tid + i * 256;
            int row = f4 >> 3;        // 0..63
            int kq  = f4 & 7;
            float4 v = *(const float4*)&W[(bp + row) * DIN + k0 + kq * 4];
            Bs[kq*4+0][row] = v.x; Bs[kq*4+1][row] = v.y;
            Bs[kq*4+2][row] = v.z; Bs[kq*4+3][row] = v.w;
        }
        __syncthreads();

#pragma unroll
        for (int kk = 0; kk < BK; kk++) {
            float a[8], bb[4];
            *(float4*)&a[0] = *(const float4*)&As[kk][tm];
            *(float4*)&a[4] = *(const float4*)&As[kk][tm + 4];
            *(float4*)&bb[0] = *(const float4*)&Bs[kk][tp];
#pragma unroll
            for (int i = 0; i < 8; i++)
#pragma unroll
                for (int j = 0; j < 4; j++)
                    acc[i][j] = fmaf(a[i], bb[j], acc[i][j]);
        }
        __syncthreads();
    }

    float4 bv = *(const float4*)&bias[bp + tp];
#pragma unroll
    for (int i = 0; i < 8; i++) {
        float4 o;
        o.x = acc[i][0] + bv.x; o.y = acc[i][1] + bv.y;
        o.z = acc[i][2] + bv.z; o.w = acc[i][3] + bv.w;
        *(float4*)&g_delta[(bm + tm + i) * PAIRS + bp + tp] = o;
    }
}

// ---------------------------------------------------------------------------
// Pass 1: per-chunk sums.  grid = BATCH*NCHUNK blocks, 256 threads (one per p)
// ---------------------------------------------------------------------------
__global__ void chunksum_kernel() {
    int bc = blockIdx.x;           // b*NCHUNK + c
    int b = bc >> 6, c = bc & 63;
    int p = threadIdx.x;
    const float* d = g_delta + ((b * SEQ + c * TCHUNK) * PAIRS) + p;
    float s = 0.f;
#pragma unroll 8
    for (int i = 0; i < TCHUNK; i++) s += d[i * PAIRS];
    g_csum[bc * PAIRS + p] = s;
}

// ---------------------------------------------------------------------------
// Pass 2: exclusive scan of chunk sums along c.  grid = BATCH, 256 threads.
// ---------------------------------------------------------------------------
__global__ void chunkscan_kernel() {
    int b = blockIdx.x;
    int p = threadIdx.x;
    float run = 0.f;
    for (int c = 0; c < NCHUNK; c++) {
        int idx = (b * NCHUNK + c) * PAIRS + p;
        g_coff[idx] = run;
        run += g_csum[idx];
    }
}

// ---------------------------------------------------------------------------
// Accurate-range sin/cos: Cody-Waite 3-term reduction by 2*pi, then sinf/cosf
// of a small argument (safe even under fast-math __sinf/__cosf).
// ---------------------------------------------------------------------------
__device__ __forceinline__ void accurate_sincos(float ang, float* sn, float* cs) {
    const float INV_2PI = 0.15915494309189535f;
    const float C1 = 6.28125f;           // exact in fp32 (9 mantissa bits)
    const float C2 = 1.9353071795e-3f;
    const float C3 = 3.1786509424591713e-8f;
    float n = rintf(ang * INV_2PI);
    float r = ang - n * C1;
    r = r - n * C2;
    r = r - n * C3;
    *sn = sinf(r);
    *cs = cosf(r);
}

// ---------------------------------------------------------------------------
// Pass 3 (fused): local inclusive scan + rotation of first 512 dims.
// grid = BATCH*NCHUNK blocks, 256 threads (one per p).
// ---------------------------------------------------------------------------
__global__ void rotate_kernel(const float* __restrict__ x, float* __restrict__ out) {
    int bc = blockIdx.x;
    int b = bc >> 6, c = bc & 63;
    int p = threadIdx.x;
    float angle = g_coff[bc * PAIRS + p];
    int t0 = b * SEQ + c * TCHUNK;
    for (int i = 0; i < TCHUNK; i++) {
        int t = t0 + i;
        angle += g_delta[t * PAIRS + p];
        float sn, cs;
        accurate_sincos(angle, &sn, &cs);
        const float* xr = x + (size_t)t * DIN;
        float x1 = xr[p];
        float x2 = xr[PAIRS + p];
        float* orow = out + (size_t)t * DIN;
        orow[p]         = x1 * cs - x2 * sn;
        orow[PAIRS + p] = x2 * cs + x1 * sn;
    }
}

// ---------------------------------------------------------------------------
// Tail copy: dims [512, 2048) of every row.  1536 floats = 384 float4 per row.
// grid = MROWS blocks, 128 threads, 3 float4 each.
// ---------------------------------------------------------------------------
__global__ void copy_kernel(const float* __restrict__ x, float* __restrict__ out) {
    size_t base = (size_t)blockIdx.x * (DIN / 4) + (512 / 4);
    const float4* xs = (const float4*)x + base;
    float4* os = (float4*)out + base;
#pragma unroll
    for (int k = 0; k < 3; k++)
        os[threadIdx.x + 128 * k] = xs[threadIdx.x + 128 * k];
}

extern "C" void kernel_launch(void* const* d_in, const int* in_sizes, int n_in,
                              void* d_out, int out_size) {
    const float* x    = (const float*)d_in[0];
    const float* W    = (const float*)d_in[1];
    const float* bias = (const float*)d_in[2];
    float* out = (float*)d_out;

    dim3 ggrid(PAIRS / BP, MROWS / BM);   // (4, 128)
    gemm_kernel<<<ggrid, 256>>>(x, W, bias);
    chunksum_kernel<<<BATCH * NCHUNK, 256>>>();
    chunkscan_kernel<<<BATCH, 256>>>();
    rotate_kernel<<<BATCH * NCHUNK, 256>>>(x, out);
    copy_kernel<<<MROWS, 128>>>(x, out);
}

// round 3
// speedup vs baseline: 2.3913x; 2.3913x over previous
#include <cuda_runtime.h>
#include <cuda_fp16.h>
#include <math.h>
#include <cstdint>

// ---------------------------------------------------------------------------
// Problem constants
// ---------------------------------------------------------------------------
#define BATCH 4
#define SEQ   4096
#define DIN   2048
#define PAIRS 256
#define MROWS (BATCH*SEQ)      // 16384
#define NCHUNK 128
#define TCHUNK (SEQ/NCHUNK)    // 32

// Scratch (device globals: no allocation allowed)
__device__ float g_delta[MROWS * PAIRS];        // 16.8 MB [m][p]
__device__ float g_csum [BATCH * NCHUNK * PAIRS];
__device__ float g_coff [BATCH * NCHUNK * PAIRS];
__device__ __half g_Wh[PAIRS * DIN];            // W*64 hi split
__device__ __half g_Wl[PAIRS * DIN];            // W*64 lo split

// ---------------------------------------------------------------------------
// fp16 helpers
// ---------------------------------------------------------------------------
__device__ __forceinline__ uint32_t pkh(__half a, __half b) {
    __half2 t = __halves2half2(a, b);
    return *(uint32_t*)&t;
}

// ---------------------------------------------------------------------------
// W split: W scaled by 64 (exact pow2; epilogue multiplies by 1/64) so the
// low split stays in fp16 normal range. 524288 elems, 512 blk x 256 thr x 4.
// ---------------------------------------------------------------------------
__global__ void wsplit_kernel(const float* __restrict__ W) {
    int i4 = blockIdx.x * 256 + threadIdx.x;
    float4 v = ((const float4*)W)[i4];
    float a[4] = {v.x * 64.f, v.y * 64.f, v.z * 64.f, v.w * 64.f};
    __half h[4], l[4];
#pragma unroll
    for (int e = 0; e < 4; e++) {
        h[e] = __float2half_rn(a[e]);
        l[e] = __float2half_rn(a[e] - __half2float(h[e]));
    }
    ((uint2*)g_Wh)[i4] = make_uint2(pkh(h[0], h[1]), pkh(h[2], h[3]));
    ((uint2*)g_Wl)[i4] = make_uint2(pkh(l[0], l[1]), pkh(l[2], l[3]));
}

// ---------------------------------------------------------------------------
// mma.sync GEMM: delta = X @ W^T (+bias in epilogue), 3-product fp16 split.
// BM=128, BN=128, BK=32, 8 warps (2x4), warp tile 64x32.
// SMEM rows padded to 40 halves (80B) -> conflict-free ldmatrix.
// ---------------------------------------------------------------------------
#define BM 128
#define BN 128
#define BK 32
#define ROWH 40                 // halves per smem row (80 bytes)
#define REGH (128 * ROWH)       // halves per (buf,split) region = 5120
#define SMEM_BYTES (8 * REGH * 2)  // 4 A regions + 4 B regions = 81920 B

#define LDSM_X4(r0, r1, r2, r3, addr) \
    asm volatile("ldmatrix.sync.aligned.m8n8.x4.shared.b16 {%0,%1,%2,%3}, [%4];" \
                 : "=r"(r0), "=r"(r1), "=r"(r2), "=r"(r3) : "r"(addr))

#define MMA16816(d, a, b0, b1) \
    asm volatile("mma.sync.aligned.m16n8k16.row.col.f32.f16.f16.f32 " \
                 "{%0,%1,%2,%3}, {%4,%5,%6,%7}, {%8,%9}, {%0,%1,%2,%3};" \
                 : "+f"((d)[0]), "+f"((d)[1]), "+f"((d)[2]), "+f"((d)[3]) \
                 : "r"((a)[0]), "r"((a)[1]), "r"((a)[2]), "r"((a)[3]), \
                   "r"(b0), "r"(b1))

__global__ __launch_bounds__(256, 1)
void gemm_kernel(const float* __restrict__ X, const float* __restrict__ bias) {
    extern __shared__ __half sh[];
    const int tid = threadIdx.x, lane = tid & 31, wid = tid >> 5;
    const int m0 = blockIdx.y * BM, n0 = blockIdx.x * BN;
    const int wm = (wid & 1) * 64, wn = (wid >> 1) * 32;
    const uint32_t sbase = (uint32_t)__cvta_generic_to_shared(sh);

    float acc[4][4][4];
#pragma unroll
    for (int i = 0; i < 4; i++)
#pragma unroll
        for (int j = 0; j < 4; j++)
#pragma unroll
            for (int r = 0; r < 4; r++) acc[i][j][r] = 0.f;

    float4 xa[4];
    uint4 wreg[2][2];

    // ---- staging helpers ----
#define LDG_TILE(k0) do {                                                      \
    _Pragma("unroll")                                                          \
    for (int i = 0; i < 4; i++) {                                              \
        int f = tid + i * 256; int r = f >> 3, q = f & 7;                      \
        xa[i] = *(const float4*)(X + (size_t)(m0 + r) * DIN + (k0) + q * 4);   \
    }                                                                          \
    _Pragma("unroll")                                                          \
    for (int i = 0; i < 2; i++) {                                              \
        int f = tid + i * 256; int r = f >> 2, q = f & 3;                      \
        wreg[0][i] = *(const uint4*)(g_Wh + (size_t)(n0 + r) * DIN + (k0) + q * 8); \
        wreg[1][i] = *(const uint4*)(g_Wl + (size_t)(n0 + r) * DIN + (k0) + q * 8); \
    }                                                                          \
} while (0)

#define STS_TILE(buf) do {                                                     \
    _Pragma("unroll")                                                          \
    for (int i = 0; i < 4; i++) {                                              \
        int f = tid + i * 256; int r = f >> 3, q = f & 7;                      \
        float4 v = xa[i];                                                      \
        __half h0 = __float2half_rn(v.x), h1 = __float2half_rn(v.y);           \
        __half h2 = __float2half_rn(v.z), h3 = __float2half_rn(v.w);           \
        __half l0 = __float2half_rn(v.x - __half2float(h0));                   \
        __half l1 = __float2half_rn(v.y - __half2float(h1));                   \
        __half l2 = __float2half_rn(v.z - __half2float(h2));                   \
        __half l3 = __float2half_rn(v.w - __half2float(h3));                   \
        int off = r * ROWH + q * 4;                                            \
        *(uint2*)(sh + ((buf) * 2 + 0) * REGH + off) =                         \
            make_uint2(pkh(h0, h1), pkh(h2, h3));                              \
        *(uint2*)(sh + ((buf) * 2 + 1) * REGH + off) =                         \
            make_uint2(pkh(l0, l1), pkh(l2, l3));                              \
    }                                                                          \
    _Pragma("unroll")                                                          \
    for (int i = 0; i < 2; i++) {                                              \
        int f = tid + i * 256; int r = f >> 2, q = f & 3;                      \
        int off = r * ROWH + q * 8;                                            \
        *(uint4*)(sh + (4 + (buf) * 2 + 0) * REGH + off) = wreg[0][i];         \
        *(uint4*)(sh + (4 + (buf) * 2 + 1) * REGH + off) = wreg[1][i];         \
    }                                                                          \
} while (0)

    LDG_TILE(0);
    STS_TILE(0);
    __syncthreads();

    for (int c = 0; c < DIN / BK; c++) {
        const int buf = c & 1;
        if (c + 1 < DIN / BK) LDG_TILE((c + 1) * BK);

#pragma unroll
        for (int kk = 0; kk < 2; kk++) {
            uint32_t ah[2][4][4];     // [split][mtile][reg]
            uint32_t bh[2][2][4];     // [split][pair j][reg] (2 n8 tiles per x4)
#pragma unroll
            for (int s = 0; s < 2; s++) {
                uint32_t areg = sbase + ((buf * 2 + s) * REGH) * 2;
#pragma unroll
                for (int i = 0; i < 4; i++) {
                    int row = wm + i * 16 + (lane & 15);
                    int col = kk * 16 + ((lane >> 4) << 3);
                    uint32_t addr = areg + row * 80 + col * 2;
                    LDSM_X4(ah[s][i][0], ah[s][i][1], ah[s][i][2], ah[s][i][3], addr);
                }
                uint32_t breg = sbase + ((4 + buf * 2 + s) * REGH) * 2;
#pragma unroll
                for (int j = 0; j < 2; j++) {
                    int grp = lane >> 3, ii = lane & 7;
                    int row = wn + j * 16 + ((grp >> 1) << 3) + ii;
                    int col = kk * 16 + ((grp & 1) << 3);
                    uint32_t addr = breg + row * 80 + col * 2;
                    LDSM_X4(bh[s][j][0], bh[s][j][1], bh[s][j][2], bh[s][j][3], addr);
                }
            }
#pragma unroll
            for (int i = 0; i < 4; i++)
#pragma unroll
                for (int jt = 0; jt < 4; jt++) {
                    uint32_t b0h = bh[0][jt >> 1][(jt & 1) * 2];
                    uint32_t b1h = bh[0][jt >> 1][(jt & 1) * 2 + 1];
                    uint32_t b0l = bh[1][jt >> 1][(jt & 1) * 2];
                    uint32_t b1l = bh[1][jt >> 1][(jt & 1) * 2 + 1];
                    MMA16816(acc[i][jt], ah[0][i], b0h, b1h);   // Xh*Wh
                    MMA16816(acc[i][jt], ah[0][i], b0l, b1l);   // Xh*Wl
                    MMA16816(acc[i][jt], ah[1][i], b0h, b1h);   // Xl*Wh
                }
        }

        if (c + 1 < DIN / BK) STS_TILE(buf ^ 1);
        __syncthreads();
    }

    // epilogue: undo W*64 scale, add bias, write g_delta
    const float inv64 = 0.015625f;
#pragma unroll
    for (int i = 0; i < 4; i++) {
        int row = m0 + wm + i * 16 + (lane >> 2);
#pragma unroll
        for (int jt = 0; jt < 4; jt++) {
            int col = n0 + wn + jt * 8 + (lane & 3) * 2;
            float2 bv = *(const float2*)(bias + col);
            float2 o0, o1;
            o0.x = acc[i][jt][0] * inv64 + bv.x;
            o0.y = acc[i][jt][1] * inv64 + bv.y;
            o1.x = acc[i][jt][2] * inv64 + bv.x;
            o1.y = acc[i][jt][3] * inv64 + bv.y;
            *(float2*)(g_delta + (size_t)row * PAIRS + col) = o0;
            *(float2*)(g_delta + (size_t)(row + 8) * PAIRS + col) = o1;
        }
    }
#undef LDG_TILE
#undef STS_TILE
}

// ---------------------------------------------------------------------------
// Pass 1: per-chunk sums
// ---------------------------------------------------------------------------
__global__ void chunksum_kernel() {
    int bc = blockIdx.x;
    int b = bc >> 7, c = bc & 127;
    int p = threadIdx.x;
    const float* d = g_delta + ((size_t)(b * SEQ + c * TCHUNK) * PAIRS) + p;
    float s = 0.f;
#pragma unroll 8
    for (int i = 0; i < TCHUNK; i++) s += d[(size_t)i * PAIRS];
    g_csum[bc * PAIRS + p] = s;
}

// ---------------------------------------------------------------------------
// Pass 2: exclusive scan of chunk sums
// ---------------------------------------------------------------------------
__global__ void chunkscan_kernel() {
    int b = blockIdx.x;
    int p = threadIdx.x;
    float run = 0.f;
#pragma unroll 8
    for (int c = 0; c < NCHUNK; c++) {
        int idx = (b * NCHUNK + c) * PAIRS + p;
        g_coff[idx] = run;
        run += g_csum[idx];
    }
}

// ---------------------------------------------------------------------------
// Accurate large-range sincos (Cody-Waite 3-term 2pi reduction)
// ---------------------------------------------------------------------------
__device__ __forceinline__ void accurate_sincos(float ang, float* sn, float* cs) {
    const float INV_2PI = 0.15915494309189535f;
    const float C1 = 6.28125f;
    const float C2 = 1.9353071795e-3f;
    const float C3 = 3.1786509424591713e-8f;
    float n = rintf(ang * INV_2PI);
    float r = ang - n * C1;
    r = r - n * C2;
    r = r - n * C3;
    *sn = sinf(r);
    *cs = cosf(r);
}

// ---------------------------------------------------------------------------
// Pass 3: local scan + rotation + fused tail copy (whole output row)
// ---------------------------------------------------------------------------
__global__ void rotate_kernel(const float* __restrict__ x, float* __restrict__ out) {
    int bc = blockIdx.x;
    int b = bc >> 7, c = bc & 127;
    int p = threadIdx.x;
    float angle = g_coff[bc * PAIRS + p];
    int t0 = b * SEQ + c * TCHUNK;
    for (int i = 0; i < TCHUNK; i++) {
        int t = t0 + i;
        angle += g_delta[(size_t)t * PAIRS + p];
        float sn, cs;
        accurate_sincos(angle, &sn, &cs);
        const float* xr = x + (size_t)t * DIN;
        float* orow = out + (size_t)t * DIN;
        float x1 = xr[p];
        float x2 = xr[PAIRS + p];
        orow[p]         = x1 * cs - x2 * sn;
        orow[PAIRS + p] = x2 * cs + x1 * sn;
#pragma unroll
        for (int j = 0; j < 6; j++) {
            int idx = 512 + j * 256 + p;
            orow[idx] = xr[idx];
        }
    }
}

extern "C" void kernel_launch(void* const* d_in, const int* in_sizes, int n_in,
                              void* d_out, int out_size) {
    const float* x    = (const float*)d_in[0];
    const float* W    = (const float*)d_in[1];
    const float* bias = (const float*)d_in[2];
    float* out = (float*)d_out;

    cudaFuncSetAttribute(gemm_kernel, cudaFuncAttributeMaxDynamicSharedMemorySize,
                         SMEM_BYTES);

    wsplit_kernel<<<512, 256>>>(W);
    gemm_kernel<<<dim3(PAIRS / BN, MROWS / BM), 256, SMEM_BYTES>>>(x, bias);
    chunksum_kernel<<<BATCH * NCHUNK, 256>>>();
    chunkscan_kernel<<<BATCH, 256>>>();
    rotate_kernel<<<BATCH * NCHUNK, 256>>>(x, out);
}

// round 4
// speedup vs baseline: 2.6745x; 1.1184x over previous
#include <cuda_runtime.h>
#include <cuda_fp16.h>
#include <math.h>
#include <cstdint>

// ---------------------------------------------------------------------------
// Problem constants
// ---------------------------------------------------------------------------
#define BATCH 4
#define SEQ   4096
#define DIN   2048
#define PAIRS 256
#define MROWS (BATCH*SEQ)      // 16384
#define NCHUNK 128
#define TCHUNK (SEQ/NCHUNK)    // 32

// Scratch (device globals: no allocation allowed)
__device__ float g_delta[MROWS * PAIRS];        // 16.8 MB [m][p]
__device__ float g_csum [BATCH * PAIRS * NCHUNK];  // transposed [b][p][c]
__device__ float g_coff [BATCH * PAIRS * NCHUNK];  // transposed [b][p][c]
__device__ __half g_Wh[PAIRS * DIN];            // W*64 hi split
__device__ __half g_Wl[PAIRS * DIN];            // W*64 lo split

// ---------------------------------------------------------------------------
// fp16 helpers
// ---------------------------------------------------------------------------
__device__ __forceinline__ uint32_t pkh(__half a, __half b) {
    __half2 t = __halves2half2(a, b);
    return *(uint32_t*)&t;
}

// ---------------------------------------------------------------------------
// W split: W scaled by 64 (exact pow2; epilogue multiplies by 1/64) so the
// low split stays in fp16 normal range. 524288 elems, 512 blk x 256 thr x 4.
// ---------------------------------------------------------------------------
__global__ void wsplit_kernel(const float* __restrict__ W) {
    int i4 = blockIdx.x * 256 + threadIdx.x;
    float4 v = ((const float4*)W)[i4];
    float a[4] = {v.x * 64.f, v.y * 64.f, v.z * 64.f, v.w * 64.f};
    __half h[4], l[4];
#pragma unroll
    for (int e = 0; e < 4; e++) {
        h[e] = __float2half_rn(a[e]);
        l[e] = __float2half_rn(a[e] - __half2float(h[e]));
    }
    ((uint2*)g_Wh)[i4] = make_uint2(pkh(h[0], h[1]), pkh(h[2], h[3]));
    ((uint2*)g_Wl)[i4] = make_uint2(pkh(l[0], l[1]), pkh(l[2], l[3]));
}

// ---------------------------------------------------------------------------
// mma.sync GEMM: delta = X @ W^T (+bias in epilogue), 3-product fp16 split.
// BM=128, BN=128, BK=32, 8 warps (2x4), warp tile 64x32.
// SMEM rows padded to 40 halves (80B) -> conflict-free ldmatrix.
// ---------------------------------------------------------------------------
#define BM 128
#define BN 128
#define BK 32
#define ROWH 40                 // halves per smem row (80 bytes)
#define REGH (128 * ROWH)       // halves per (buf,split) region = 5120
#define SMEM_BYTES (8 * REGH * 2)  // 4 A regions + 4 B regions = 81920 B

#define LDSM_X4(r0, r1, r2, r3, addr) \
    asm volatile("ldmatrix.sync.aligned.m8n8.x4.shared.b16 {%0,%1,%2,%3}, [%4];" \
                 : "=r"(r0), "=r"(r1), "=r"(r2), "=r"(r3) : "r"(addr))

#define MMA16816(d, a, b0, b1) \
    asm volatile("mma.sync.aligned.m16n8k16.row.col.f32.f16.f16.f32 " \
                 "{%0,%1,%2,%3}, {%4,%5,%6,%7}, {%8,%9}, {%0,%1,%2,%3};" \
                 : "+f"((d)[0]), "+f"((d)[1]), "+f"((d)[2]), "+f"((d)[3]) \
                 : "r"((a)[0]), "r"((a)[1]), "r"((a)[2]), "r"((a)[3]), \
                   "r"(b0), "r"(b1))

__global__ __launch_bounds__(256, 1)
void gemm_kernel(const float* __restrict__ X, const float* __restrict__ bias) {
    extern __shared__ __half sh[];
    const int tid = threadIdx.x, lane = tid & 31, wid = tid >> 5;
    const int m0 = blockIdx.y * BM, n0 = blockIdx.x * BN;
    const int wm = (wid & 1) * 64, wn = (wid >> 1) * 32;
    const uint32_t sbase = (uint32_t)__cvta_generic_to_shared(sh);

    float acc[4][4][4];
#pragma unroll
    for (int i = 0; i < 4; i++)
#pragma unroll
        for (int j = 0; j < 4; j++)
#pragma unroll
            for (int r = 0; r < 4; r++) acc[i][j][r] = 0.f;

    float4 xa[4];
    uint4 wreg[2][2];

    // ---- staging helpers ----
#define LDG_TILE(k0) do {                                                      \
    _Pragma("unroll")                                                          \
    for (int i = 0; i < 4; i++) {                                              \
        int f = tid + i * 256; int r = f >> 3, q = f & 7;                      \
        xa[i] = *(const float4*)(X + (size_t)(m0 + r) * DIN + (k0) + q * 4);   \
    }                                                                          \
    _Pragma("unroll")                                                          \
    for (int i = 0; i < 2; i++) {                                              \
        int f = tid + i * 256; int r = f >> 2, q = f & 3;                      \
        wreg[0][i] = *(const uint4*)(g_Wh + (size_t)(n0 + r) * DIN + (k0) + q * 8); \
        wreg[1][i] = *(const uint4*)(g_Wl + (size_t)(n0 + r) * DIN + (k0) + q * 8); \
    }                                                                          \
} while (0)

#define STS_TILE(buf) do {                                                     \
    _Pragma("unroll")                                                          \
    for (int i = 0; i < 4; i++) {                                              \
        int f = tid + i * 256; int r = f >> 3, q = f & 7;                      \
        float4 v = xa[i];                                                      \
        __half h0 = __float2half_rn(v.x), h1 = __float2half_rn(v.y);           \
        __half h2 = __float2half_rn(v.z), h3 = __float2half_rn(v.w);           \
        __half l0 = __float2half_rn(v.x - __half2float(h0));                   \
        __half l1 = __float2half_rn(v.y - __half2float(h1));                   \
        __half l2 = __float2half_rn(v.z - __half2float(h2));                   \
        __half l3 = __float2half_rn(v.w - __half2float(h3));                   \
        int off = r * ROWH + q * 4;                                            \
        *(uint2*)(sh + ((buf) * 2 + 0) * REGH + off) =                         \
            make_uint2(pkh(h0, h1), pkh(h2, h3));                              \
        *(uint2*)(sh + ((buf) * 2 + 1) * REGH + off) =                         \
            make_uint2(pkh(l0, l1), pkh(l2, l3));                              \
    }                                                                          \
    _Pragma("unroll")                                                          \
    for (int i = 0; i < 2; i++) {                                              \
        int f = tid + i * 256; int r = f >> 2, q = f & 3;                      \
        int off = r * ROWH + q * 8;                                            \
        *(uint4*)(sh + (4 + (buf) * 2 + 0) * REGH + off) = wreg[0][i];         \
        *(uint4*)(sh + (4 + (buf) * 2 + 1) * REGH + off) = wreg[1][i];         \
    }                                                                          \
} while (0)

    LDG_TILE(0);
    STS_TILE(0);
    __syncthreads();

    for (int c = 0; c < DIN / BK; c++) {
        const int buf = c & 1;
        if (c + 1 < DIN / BK) LDG_TILE((c + 1) * BK);

#pragma unroll
        for (int kk = 0; kk < 2; kk++) {
            uint32_t ah[2][4][4];     // [split][mtile][reg]
            uint32_t bh[2][2][4];     // [split][pair j][reg]
#pragma unroll
            for (int s = 0; s < 2; s++) {
                uint32_t areg = sbase + ((buf * 2 + s) * REGH) * 2;
#pragma unroll
                for (int i = 0; i < 4; i++) {
                    int row = wm + i * 16 + (lane & 15);
                    int col = kk * 16 + ((lane >> 4) << 3);
                    uint32_t addr = areg + row * 80 + col * 2;
                    LDSM_X4(ah[s][i][0], ah[s][i][1], ah[s][i][2], ah[s][i][3], addr);
                }
                uint32_t breg = sbase + ((4 + buf * 2 + s) * REGH) * 2;
#pragma unroll
                for (int j = 0; j < 2; j++) {
                    int grp = lane >> 3, ii = lane & 7;
                    int row = wn + j * 16 + ((grp >> 1) << 3) + ii;
                    int col = kk * 16 + ((grp & 1) << 3);
                    uint32_t addr = breg + row * 80 + col * 2;
                    LDSM_X4(bh[s][j][0], bh[s][j][1], bh[s][j][2], bh[s][j][3], addr);
                }
            }
#pragma unroll
            for (int i = 0; i < 4; i++)
#pragma unroll
                for (int jt = 0; jt < 4; jt++) {
                    uint32_t b0h = bh[0][jt >> 1][(jt & 1) * 2];
                    uint32_t b1h = bh[0][jt >> 1][(jt & 1) * 2 + 1];
                    uint32_t b0l = bh[1][jt >> 1][(jt & 1) * 2];
                    uint32_t b1l = bh[1][jt >> 1][(jt & 1) * 2 + 1];
                    MMA16816(acc[i][jt], ah[0][i], b0h, b1h);   // Xh*Wh
                    MMA16816(acc[i][jt], ah[0][i], b0l, b1l);   // Xh*Wl
                    MMA16816(acc[i][jt], ah[1][i], b0h, b1h);   // Xl*Wh
                }
        }

        if (c + 1 < DIN / BK) STS_TILE(buf ^ 1);
        __syncthreads();
    }

    // epilogue: undo W*64 scale, add bias, write g_delta
    const float inv64 = 0.015625f;
#pragma unroll
    for (int i = 0; i < 4; i++) {
        int row = m0 + wm + i * 16 + (lane >> 2);
#pragma unroll
        for (int jt = 0; jt < 4; jt++) {
            int col = n0 + wn + jt * 8 + (lane & 3) * 2;
            float2 bv = *(const float2*)(bias + col);
            float2 o0, o1;
            o0.x = acc[i][jt][0] * inv64 + bv.x;
            o0.y = acc[i][jt][1] * inv64 + bv.y;
            o1.x = acc[i][jt][2] * inv64 + bv.x;
            o1.y = acc[i][jt][3] * inv64 + bv.y;
            *(float2*)(g_delta + (size_t)row * PAIRS + col) = o0;
            *(float2*)(g_delta + (size_t)(row + 8) * PAIRS + col) = o1;
        }
    }
#undef LDG_TILE
#undef STS_TILE
}

// ---------------------------------------------------------------------------
// Pass 1: per-chunk sums -> g_csum in transposed [b][p][c] layout
// ---------------------------------------------------------------------------
__global__ void chunksum_kernel() {
    int bc = blockIdx.x;
    int b = bc >> 7, c = bc & 127;
    int p = threadIdx.x;
    const float* d = g_delta + ((size_t)(b * SEQ + c * TCHUNK) * PAIRS) + p;
    float s = 0.f;
#pragma unroll 8
    for (int i = 0; i < TCHUNK; i++) s += d[(size_t)i * PAIRS];
    g_csum[(size_t)(b * PAIRS + p) * NCHUNK + c] = s;
}

// ---------------------------------------------------------------------------
// Pass 2: warp-parallel exclusive scan. One warp per (b,p); 1024 warps.
// Lane handles 4 consecutive chunks (coalesced float4 in transposed layout).
// ---------------------------------------------------------------------------
__global__ void chunkscan_kernel() {
    int w = (blockIdx.x * blockDim.x + threadIdx.x) >> 5;   // 0..1023 = b*256+p
    int lane = threadIdx.x & 31;
    float4 v = *(const float4*)(g_csum + (size_t)w * NCHUNK + lane * 4);
    float s0 = v.x;
    float s1 = s0 + v.y;
    float s2 = s1 + v.z;
    float s3 = s2 + v.w;
    float run = s3;
#pragma unroll
    for (int d = 1; d < 32; d <<= 1) {
        float o = __shfl_up_sync(0xFFFFFFFFu, run, d);
        if (lane >= d) run += o;
    }
    float excl = run - s3;
    float4 o;
    o.x = excl;
    o.y = excl + s0;
    o.z = excl + s1;
    o.w = excl + s2;
    *(float4*)(g_coff + (size_t)w * NCHUNK + lane * 4) = o;
}

// ---------------------------------------------------------------------------
// Accurate large-range sincos (Cody-Waite 3-term 2pi reduction)
// ---------------------------------------------------------------------------
__device__ __forceinline__ void accurate_sincos(float ang, float* sn, float* cs) {
    const float INV_2PI = 0.15915494309189535f;
    const float C1 = 6.28125f;
    const float C2 = 1.9353071795e-3f;
    const float C3 = 3.1786509424591713e-8f;
    float n = rintf(ang * INV_2PI);
    float r = ang - n * C1;
    r = r - n * C2;
    r = r - n * C3;
    *sn = sinf(r);
    *cs = cosf(r);
}

// ---------------------------------------------------------------------------
// Pass 3: local scan + rotation + fused tail copy (whole output row)
// ---------------------------------------------------------------------------
__global__ void rotate_kernel(const float* __restrict__ x, float* __restrict__ out) {
    int bc = blockIdx.x;
    int b = bc >> 7, c = bc & 127;
    int p = threadIdx.x;
    float angle = g_coff[(size_t)(b * PAIRS + p) * NCHUNK + c];
    int t0 = b * SEQ + c * TCHUNK;
    for (int i = 0; i < TCHUNK; i++) {
        int t = t0 + i;
        angle += g_delta[(size_t)t * PAIRS + p];
        float sn, cs;
        accurate_sincos(angle, &sn, &cs);
        const float* xr = x + (size_t)t * DIN;
        float* orow = out + (size_t)t * DIN;
        float x1 = xr[p];
        float x2 = xr[PAIRS + p];
        orow[p]         = x1 * cs - x2 * sn;
        orow[PAIRS + p] = x2 * cs + x1 * sn;
#pragma unroll
        for (int j = 0; j < 6; j++) {
            int idx = 512 + j * 256 + p;
            orow[idx] = xr[idx];
        }
    }
}

extern "C" void kernel_launch(void* const* d_in, const int* in_sizes, int n_in,
                              void* d_out, int out_size) {
    const float* x    = (const float*)d_in[0];
    const float* W    = (const float*)d_in[1];
    const float* bias = (const float*)d_in[2];
    float* out = (float*)d_out;

    cudaFuncSetAttribute(gemm_kernel, cudaFuncAttributeMaxDynamicSharedMemorySize,
                         SMEM_BYTES);

    wsplit_kernel<<<512, 256>>>(W);
    gemm_kernel<<<dim3(PAIRS / BN, MROWS / BM), 256, SMEM_BYTES>>>(x, bias);
    chunksum_kernel<<<BATCH * NCHUNK, 256>>>();
    chunkscan_kernel<<<128, 256>>>();
    rotate_kernel<<<BATCH * NCHUNK, 256>>>(x, out);
}

// round 5
// speedup vs baseline: 2.7648x; 1.0338x over previous
#include <cuda_runtime.h>
#include <cuda_fp16.h>
#include <math.h>
#include <cstdint>

// ---------------------------------------------------------------------------
// Problem constants
// ---------------------------------------------------------------------------
#define BATCH 4
#define SEQ   4096
#define DIN   2048
#define PAIRS 256
#define MROWS (BATCH*SEQ)      // 16384
#define NCHUNK 128
#define TCHUNK (SEQ/NCHUNK)    // 32

// Scratch (device globals: no allocation allowed)
__device__ float g_delta[MROWS * PAIRS];           // 16.8 MB [m][p]
__device__ float g_csum [BATCH * NCHUNK * PAIRS];  // [b][c][p]
__device__ float g_coff [BATCH * NCHUNK * PAIRS];  // [b][c][p]
__device__ __half g_Wh[PAIRS * DIN];               // W*64 hi split
__device__ __half g_Wl[PAIRS * DIN];               // W*64 lo split

// ---------------------------------------------------------------------------
// fp16 helpers
// ---------------------------------------------------------------------------
__device__ __forceinline__ uint32_t pkh(__half a, __half b) {
    __half2 t = __halves2half2(a, b);
    return *(uint32_t*)&t;
}

// ---------------------------------------------------------------------------
// W split: W scaled by 64 (exact pow2; epilogue multiplies by 1/64) so the
// low split stays in fp16 normal range. 524288 elems, 512 blk x 256 thr x 4.
// ---------------------------------------------------------------------------
__global__ void wsplit_kernel(const float* __restrict__ W) {
    int i4 = blockIdx.x * 256 + threadIdx.x;
    float4 v = ((const float4*)W)[i4];
    float a[4] = {v.x * 64.f, v.y * 64.f, v.z * 64.f, v.w * 64.f};
    __half h[4], l[4];
#pragma unroll
    for (int e = 0; e < 4; e++) {
        h[e] = __float2half_rn(a[e]);
        l[e] = __float2half_rn(a[e] - __half2float(h[e]));
    }
    ((uint2*)g_Wh)[i4] = make_uint2(pkh(h[0], h[1]), pkh(h[2], h[3]));
    ((uint2*)g_Wl)[i4] = make_uint2(pkh(l[0], l[1]), pkh(l[2], l[3]));
}

// ---------------------------------------------------------------------------
// mma.sync GEMM: delta = X @ W^T (+bias), 3-product fp16 split.
// BM=128, BN=128, BK=32, 8 warps (2x4), warp tile 64x32.
// Fused epilogue also emits per-chunk sums (chunk = 32 rows).
// ---------------------------------------------------------------------------
#define BM 128
#define BN 128
#define BK 32
#define ROWH 40                 // halves per smem row (80 bytes)
#define REGH (128 * ROWH)       // halves per (buf,split) region = 5120
#define SMEM_BYTES (8 * REGH * 2)  // 81920 B

#define LDSM_X4(r0, r1, r2, r3, addr) \
    asm volatile("ldmatrix.sync.aligned.m8n8.x4.shared.b16 {%0,%1,%2,%3}, [%4];" \
                 : "=r"(r0), "=r"(r1), "=r"(r2), "=r"(r3) : "r"(addr))

#define MMA16816(d, a, b0, b1) \
    asm volatile("mma.sync.aligned.m16n8k16.row.col.f32.f16.f16.f32 " \
                 "{%0,%1,%2,%3}, {%4,%5,%6,%7}, {%8,%9}, {%0,%1,%2,%3};" \
                 : "+f"((d)[0]), "+f"((d)[1]), "+f"((d)[2]), "+f"((d)[3]) \
                 : "r"((a)[0]), "r"((a)[1]), "r"((a)[2]), "r"((a)[3]), \
                   "r"(b0), "r"(b1))

__global__ __launch_bounds__(256, 1)
void gemm_kernel(const float* __restrict__ X, const float* __restrict__ bias) {
    extern __shared__ __half sh[];
    const int tid = threadIdx.x, lane = tid & 31, wid = tid >> 5;
    const int m0 = blockIdx.y * BM, n0 = blockIdx.x * BN;
    const int wm = (wid & 1) * 64, wn = (wid >> 1) * 32;
    const uint32_t sbase = (uint32_t)__cvta_generic_to_shared(sh);

    float acc[4][4][4];
#pragma unroll
    for (int i = 0; i < 4; i++)
#pragma unroll
        for (int j = 0; j < 4; j++)
#pragma unroll
            for (int r = 0; r < 4; r++) acc[i][j][r] = 0.f;

    float4 xa[4];
    uint4 wreg[2][2];

#define LDG_TILE(k0) do {                                                      \
    _Pragma("unroll")                                                          \
    for (int i = 0; i < 4; i++) {                                              \
        int f = tid + i * 256; int r = f >> 3, q = f & 7;                      \
        xa[i] = *(const float4*)(X + (size_t)(m0 + r) * DIN + (k0) + q * 4);   \
    }                                                                          \
    _Pragma("unroll")                                                          \
    for (int i = 0; i < 2; i++) {                                              \
        int f = tid + i * 256; int r = f >> 2, q = f & 3;                      \
        wreg[0][i] = *(const uint4*)(g_Wh + (size_t)(n0 + r) * DIN + (k0) + q * 8); \
        wreg[1][i] = *(const uint4*)(g_Wl + (size_t)(n0 + r) * DIN + (k0) + q * 8); \
    }                                                                          \
} while (0)

#define STS_TILE(buf) do {                                                     \
    _Pragma("unroll")                                                          \
    for (int i = 0; i < 4; i++) {                                              \
        int f = tid + i * 256; int r = f >> 3, q = f & 7;                      \
        float4 v = xa[i];                                                      \
        __half h0 = __float2half_rn(v.x), h1 = __float2half_rn(v.y);           \
        __half h2 = __float2half_rn(v.z), h3 = __float2half_rn(v.w);           \
        __half l0 = __float2half_rn(v.x - __half2float(h0));                   \
        __half l1 = __float2half_rn(v.y - __half2float(h1));                   \
        __half l2 = __float2half_rn(v.z - __half2float(h2));                   \
        __half l3 = __float2half_rn(v.w - __half2float(h3));                   \
        int off = r * ROWH + q * 4;                                            \
        *(uint2*)(sh + ((buf) * 2 + 0) * REGH + off) =                         \
            make_uint2(pkh(h0, h1), pkh(h2, h3));                              \
        *(uint2*)(sh + ((buf) * 2 + 1) * REGH + off) =                         \
            make_uint2(pkh(l0, l1), pkh(l2, l3));                              \
    }                                                                          \
    _Pragma("unroll")                                                          \
    for (int i = 0; i < 2; i++) {                                              \
        int f = tid + i * 256; int r = f >> 2, q = f & 3;                      \
        int off = r * ROWH + q * 8;                                            \
        *(uint4*)(sh + (4 + (buf) * 2 + 0) * REGH + off) = wreg[0][i];         \
        *(uint4*)(sh + (4 + (buf) * 2 + 1) * REGH + off) = wreg[1][i];         \
    }                                                                          \
} while (0)

    LDG_TILE(0);
    STS_TILE(0);
    __syncthreads();

    for (int c = 0; c < DIN / BK; c++) {
        const int buf = c & 1;
        if (c + 1 < DIN / BK) LDG_TILE((c + 1) * BK);

#pragma unroll
        for (int kk = 0; kk < 2; kk++) {
            uint32_t ah[2][4][4];
            uint32_t bh[2][2][4];
#pragma unroll
            for (int s = 0; s < 2; s++) {
                uint32_t areg = sbase + ((buf * 2 + s) * REGH) * 2;
#pragma unroll
                for (int i = 0; i < 4; i++) {
                    int row = wm + i * 16 + (lane & 15);
                    int col = kk * 16 + ((lane >> 4) << 3);
                    uint32_t addr = areg + row * 80 + col * 2;
                    LDSM_X4(ah[s][i][0], ah[s][i][1], ah[s][i][2], ah[s][i][3], addr);
                }
                uint32_t breg = sbase + ((4 + buf * 2 + s) * REGH) * 2;
#pragma unroll
                for (int j = 0; j < 2; j++) {
                    int grp = lane >> 3, ii = lane & 7;
                    int row = wn + j * 16 + ((grp >> 1) << 3) + ii;
                    int col = kk * 16 + ((grp & 1) << 3);
                    uint32_t addr = breg + row * 80 + col * 2;
                    LDSM_X4(bh[s][j][0], bh[s][j][1], bh[s][j][2], bh[s][j][3], addr);
                }
            }
#pragma unroll
            for (int i = 0; i < 4; i++)
#pragma unroll
                for (int jt = 0; jt < 4; jt++) {
                    uint32_t b0h = bh[0][jt >> 1][(jt & 1) * 2];
                    uint32_t b1h = bh[0][jt >> 1][(jt & 1) * 2 + 1];
                    uint32_t b0l = bh[1][jt >> 1][(jt & 1) * 2];
                    uint32_t b1l = bh[1][jt >> 1][(jt & 1) * 2 + 1];
                    MMA16816(acc[i][jt], ah[0][i], b0h, b1h);   // Xh*Wh
                    MMA16816(acc[i][jt], ah[0][i], b0l, b1l);   // Xh*Wl
                    MMA16816(acc[i][jt], ah[1][i], b0h, b1h);   // Xl*Wh
                }
        }

        if (c + 1 < DIN / BK) STS_TILE(buf ^ 1);
        __syncthreads();
    }

    // ---- epilogue 1: undo W*64 scale, add bias, write g_delta ----
    const float inv64 = 0.015625f;
#pragma unroll
    for (int i = 0; i < 4; i++) {
        int row = m0 + wm + i * 16 + (lane >> 2);
#pragma unroll
        for (int jt = 0; jt < 4; jt++) {
            int col = n0 + wn + jt * 8 + (lane & 3) * 2;
            float2 bv = *(const float2*)(bias + col);
            float2 o0, o1;
            o0.x = acc[i][jt][0] * inv64 + bv.x;
            o0.y = acc[i][jt][1] * inv64 + bv.y;
            o1.x = acc[i][jt][2] * inv64 + bv.x;
            o1.y = acc[i][jt][3] * inv64 + bv.y;
            *(float2*)(g_delta + (size_t)row * PAIRS + col) = o0;
            *(float2*)(g_delta + (size_t)(row + 8) * PAIRS + col) = o1;
        }
    }

    // ---- epilogue 2: fused chunk sums (chunk = 32 rows) ----
    // Warp covers 64 rows = 2 chunks. Per column parity, sum rows in-thread,
    // then shfl_xor over the 8 lanes sharing (lane&3).
    float cs[2][4][2];
#pragma unroll
    for (int ch = 0; ch < 2; ch++)
#pragma unroll
        for (int jt = 0; jt < 4; jt++)
#pragma unroll
            for (int cp = 0; cp < 2; cp++) {
                float s = 0.f;
#pragma unroll
                for (int i2 = 0; i2 < 2; i2++) {
                    int i = ch * 2 + i2;
                    s += acc[i][jt][cp] + acc[i][jt][2 + cp];
                }
#pragma unroll
                for (int d = 4; d < 32; d <<= 1)
                    s += __shfl_xor_sync(0xFFFFFFFFu, s, d);
                cs[ch][jt][cp] = s;
            }
    if (lane < 4) {
        int b = m0 >> 12;                         // m0 / SEQ
        int cbase = ((m0 & (SEQ - 1)) >> 5) + (wm >> 5);
#pragma unroll
        for (int ch = 0; ch < 2; ch++) {
#pragma unroll
            for (int jt = 0; jt < 4; jt++) {
                int col = n0 + wn + jt * 8 + lane * 2;
                float2 bv = *(const float2*)(bias + col);
                float2 o;
                o.x = cs[ch][jt][0] * inv64 + 32.f * bv.x;
                o.y = cs[ch][jt][1] * inv64 + 32.f * bv.y;
                *(float2*)(g_csum + (size_t)(b * NCHUNK + cbase + ch) * PAIRS + col) = o;
            }
        }
    }
#undef LDG_TILE
#undef STS_TILE
}

// ---------------------------------------------------------------------------
// Chunk scan: warp per (b,p), shfl exclusive scan over 128 chunks.
// Strided scalar accesses into [b][c][p] layout (0.5 MB total, cheap).
// ---------------------------------------------------------------------------
__global__ void chunkscan_kernel() {
    int gw = (blockIdx.x * blockDim.x + threadIdx.x) >> 5;  // 0..1023
    int b = gw >> 8, p = gw & 255;
    int lane = threadIdx.x & 31;
    const float* src = g_csum + (size_t)b * NCHUNK * PAIRS + p;
    float* dst = g_coff + (size_t)b * NCHUNK * PAIRS + p;
    float v0 = src[(size_t)(lane * 4 + 0) * PAIRS];
    float v1 = src[(size_t)(lane * 4 + 1) * PAIRS];
    float v2 = src[(size_t)(lane * 4 + 2) * PAIRS];
    float v3 = src[(size_t)(lane * 4 + 3) * PAIRS];
    float s0 = v0, s1 = s0 + v1, s2 = s1 + v2, s3 = s2 + v3;
    float run = s3;
#pragma unroll
    for (int d = 1; d < 32; d <<= 1) {
        float o = __shfl_up_sync(0xFFFFFFFFu, run, d);
        if (lane >= d) run += o;
    }
    float excl = run - s3;
    dst[(size_t)(lane * 4 + 0) * PAIRS] = excl;
    dst[(size_t)(lane * 4 + 1) * PAIRS] = excl + s0;
    dst[(size_t)(lane * 4 + 2) * PAIRS] = excl + s1;
    dst[(size_t)(lane * 4 + 3) * PAIRS] = excl + s2;
}

// ---------------------------------------------------------------------------
// Accurate large-range sincos (Cody-Waite 3-term 2pi reduction)
// ---------------------------------------------------------------------------
__device__ __forceinline__ void accurate_sincos(float ang, float* sn, float* cs) {
    const float INV_2PI = 0.15915494309189535f;
    const float C1 = 6.28125f;
    const float C2 = 1.9353071795e-3f;
    const float C3 = 3.1786509424591713e-8f;
    float n = rintf(ang * INV_2PI);
    float r = ang - n * C1;
    r = r - n * C2;
    r = r - n * C3;
    *sn = sinf(r);
    *cs = cosf(r);
}

// ---------------------------------------------------------------------------
// Rotate: local scan + rotation + fused tail copy (whole output row)
// ---------------------------------------------------------------------------
__global__ void rotate_kernel(const float* __restrict__ x, float* __restrict__ out) {
    int bc = blockIdx.x;
    int b = bc >> 7, c = bc & 127;
    int p = threadIdx.x;
    float angle = g_coff[(size_t)bc * PAIRS + p];
    int t0 = b * SEQ + c * TCHUNK;
    for (int i = 0; i < TCHUNK; i++) {
        int t = t0 + i;
        angle += g_delta[(size_t)t * PAIRS + p];
        float sn, cs;
        accurate_sincos(angle, &sn, &cs);
        const float* xr = x + (size_t)t * DIN;
        float* orow = out + (size_t)t * DIN;
        float x1 = xr[p];
        float x2 = xr[PAIRS + p];
        orow[p]         = x1 * cs - x2 * sn;
        orow[PAIRS + p] = x2 * cs + x1 * sn;
#pragma unroll
        for (int j = 0; j < 6; j++) {
            int idx = 512 + j * 256 + p;
            orow[idx] = xr[idx];
        }
    }
}

extern "C" void kernel_launch(void* const* d_in, const int* in_sizes, int n_in,
                              void* d_out, int out_size) {
    const float* x    = (const float*)d_in[0];
    const float* W    = (const float*)d_in[1];
    const float* bias = (const float*)d_in[2];
    float* out = (float*)d_out;

    cudaFuncSetAttribute(gemm_kernel, cudaFuncAttributeMaxDynamicSharedMemorySize,
                         SMEM_BYTES);

    wsplit_kernel<<<512, 256>>>(W);
    gemm_kernel<<<dim3(PAIRS / BN, MROWS / BM), 256, SMEM_BYTES>>>(x, bias);
    chunkscan_kernel<<<128, 256>>>();
    rotate_kernel<<<BATCH * NCHUNK, 256>>>(x, out);
}